// round 14
// baseline (speedup 1.0000x reference)
#include <cuda_runtime.h>
#include <cuda_fp16.h>
#include <cstdint>

#define NN 100000
#define F1 128
#define HEADS 4
#define OC 32
#define NEG 0.2f
#define MAXE 1700000

// ---------------- scratch (static device globals) ----------------
__device__ __align__(16) float g_h1[NN * F1];
__device__ __align__(16) __half g_h1h[NN * F1];   // fp16 shadow for message gather
__device__ __align__(16) float g_out1[NN * F1];
__device__ __align__(16) float g_as1[NN * HEADS];
__device__ __align__(16) float g_ad1[NN * HEADS];
__device__ __align__(16) float g_h2[NN * OC];
__device__ __align__(16) __half g_h2h[NN * OC];
__device__ __align__(16) float g_as2[NN];
__device__ __align__(16) float g_ad2[NN];
__device__ int g_deg[NN];
__device__ int g_off[NN + 1];
__device__ int g_cursor[NN];
__device__ int g_bsum[1024];
__device__ int g_csr[MAXE];

__device__ __forceinline__ float lrelu(float x) { return x > 0.f ? x : NEG * x; }

// ---- packed fp32 FMA ----
__device__ __forceinline__ void ffma2(unsigned long long& acc, unsigned long long a, unsigned long long b) {
    asm("fma.rn.f32x2 %0, %1, %2, %3;" : "=l"(acc) : "l"(a), "l"(b), "l"(acc));
}
__device__ __forceinline__ unsigned long long packf2(float lo, float hi) {
    unsigned long long r;
    asm("mov.b64 %0, {%1, %2};" : "=l"(r) : "f"(lo), "f"(hi));
    return r;
}
__device__ __forceinline__ float2 unpackf2(unsigned long long v) {
    float2 r;
    asm("mov.b64 {%0, %1}, %2;" : "=f"(r.x), "=f"(r.y) : "l"(v));
    return r;
}

// ---------------- CSR build ----------------
__global__ void zero_deg(int n) {
    int i = blockIdx.x * blockDim.x + threadIdx.x;
    if (i < n) g_deg[i] = 0;
}
__global__ void hist_kernel(const int* __restrict__ dst, int e) {
    int i = blockIdx.x * blockDim.x + threadIdx.x;
    if (i < e) atomicAdd(&g_deg[dst[i]], 1);
}
__global__ void scan_block(int n) {
    __shared__ int sh[2][256];
    int t = threadIdx.x;
    int i = blockIdx.x * 256 + t;
    int val = (i < n) ? g_deg[i] : 0;
    int cur = 0;
    sh[0][t] = val;
    __syncthreads();
#pragma unroll
    for (int o = 1; o < 256; o <<= 1) {
        int v = sh[cur][t];
        if (t >= o) v += sh[cur][t - o];
        sh[cur ^ 1][t] = v;
        cur ^= 1;
        __syncthreads();
    }
    int incl = sh[cur][t];
    if (i < n) g_off[i] = incl - val;
    if (t == 255) g_bsum[blockIdx.x] = incl;
}
__global__ void scan_top(int nb) {
    __shared__ int sh[2][1024];
    int t = threadIdx.x;
    int val = (t < nb) ? g_bsum[t] : 0;
    int cur = 0;
    sh[0][t] = val;
    __syncthreads();
#pragma unroll
    for (int o = 1; o < 1024; o <<= 1) {
        int v = sh[cur][t];
        if (t >= o) v += sh[cur][t - o];
        sh[cur ^ 1][t] = v;
        cur ^= 1;
        __syncthreads();
    }
    if (t < nb) g_bsum[t] = sh[cur][t] - val;
}
__global__ void scan_add(int n, int e) {
    int i = blockIdx.x * blockDim.x + threadIdx.x;
    if (i < n) {
        int off = g_off[i] + g_bsum[i >> 8];
        g_off[i] = off;
        g_cursor[i] = off;
    }
    if (i == 0) g_off[n] = e;
}
__global__ void fill_kernel(const int* __restrict__ src, const int* __restrict__ dst, int e) {
    int i = blockIdx.x * blockDim.x + threadIdx.x;
    if (i >= e) return;
    int pos = atomicAdd(&g_cursor[dst[i]], 1);
    g_csr[pos] = src[i];
}

// ---------------- GEMM1: h1[N,128] = x[N,128] @ W1[128,128] ----------------
__global__ void gemm1_kernel(const float* __restrict__ x, const float* __restrict__ W, int n) {
    __shared__ float xs[64][68];
    __shared__ float ws[64][64];
    int tid = threadIdx.x;
    int tx = tid & 15, ty = tid >> 4;
    int row0 = blockIdx.x * 64, col0 = blockIdx.y * 64;
    unsigned long long acc2[4][2];
#pragma unroll
    for (int i = 0; i < 4; i++) { acc2[i][0] = 0ull; acc2[i][1] = 0ull; }
    for (int kt = 0; kt < 2; kt++) {
        int kb = kt * 64;
        for (int i = tid; i < 4096; i += 256) {
            int r = i >> 6, k = i & 63;
            int gr = row0 + r;
            xs[k][r] = (gr < n) ? x[gr * 128 + kb + k] : 0.f;
        }
        for (int i = tid; i < 4096; i += 256) {
            int k = i >> 6, c = i & 63;
            ws[k][c] = W[(kb + k) * 128 + col0 + c];
        }
        __syncthreads();
#pragma unroll 8
        for (int k = 0; k < 64; k++) {
            float4 a = *(const float4*)&xs[k][ty * 4];
            unsigned long long b01 = *(const unsigned long long*)&ws[k][tx * 4];
            unsigned long long b23 = *(const unsigned long long*)&ws[k][tx * 4 + 2];
            unsigned long long ad;
            ad = packf2(a.x, a.x); ffma2(acc2[0][0], ad, b01); ffma2(acc2[0][1], ad, b23);
            ad = packf2(a.y, a.y); ffma2(acc2[1][0], ad, b01); ffma2(acc2[1][1], ad, b23);
            ad = packf2(a.z, a.z); ffma2(acc2[2][0], ad, b01); ffma2(acc2[2][1], ad, b23);
            ad = packf2(a.w, a.w); ffma2(acc2[3][0], ad, b01); ffma2(acc2[3][1], ad, b23);
        }
        __syncthreads();
    }
#pragma unroll
    for (int ii = 0; ii < 4; ii++) {
        int gr = row0 + ty * 4 + ii;
        if (gr < n) {
            float2 lo = unpackf2(acc2[ii][0]);
            float2 hi = unpackf2(acc2[ii][1]);
            *(float4*)&g_h1[gr * 128 + col0 + tx * 4] = make_float4(lo.x, lo.y, hi.x, hi.y);
            __half2 p0 = __floats2half2_rn(lo.x, lo.y);
            __half2 p1 = __floats2half2_rn(hi.x, hi.y);
            *(uint2*)&g_h1h[gr * 128 + col0 + tx * 4] =
                make_uint2(*(unsigned*)&p0, *(unsigned*)&p1);
        }
    }
}

// ---------------- attention logits layer 1 ----------------
__global__ void att1_kernel(const float4* __restrict__ asr, const float4* __restrict__ adr, int n) {
    int i = blockIdx.x * blockDim.x + threadIdx.x;
    if (i >= n) return;
    const float4* hp = (const float4*)(g_h1 + (long long)i * 128);
#pragma unroll
    for (int h = 0; h < 4; h++) {
        float s = 0.f, d = 0.f;
#pragma unroll
        for (int j = 0; j < 8; j++) {
            float4 v = hp[h * 8 + j];
            float4 a = asr[h * 8 + j];
            float4 b = adr[h * 8 + j];
            s += v.x * a.x + v.y * a.y + v.z * a.z + v.w * a.w;
            d += v.x * b.x + v.y * b.y + v.z * b.z + v.w * b.w;
        }
        g_as1[i * 4 + h] = s;
        g_ad1[i * 4 + h] = d;
    }
}

// ---------------- layer1 aggregation: one warp per dst node ----------------
__global__ void agg1_kernel(const float* __restrict__ b1, int n) {
    int w = (blockIdx.x * blockDim.x + threadIdx.x) >> 5;
    int lane = threadIdx.x & 31;
    if (w >= n) return;
    int rs = g_off[w], re = g_off[w + 1];
    int h = lane >> 3;
    float4 ad4 = ((const float4*)g_ad1)[w];
    float adh = (h == 0) ? ad4.x : (h == 1) ? ad4.y : (h == 2) ? ad4.z : ad4.w;

    // pass 1: denominators (fp32)
    float4 den = make_float4(0.f, 0.f, 0.f, 0.f);
    for (int j = rs + lane; j < re; j += 32) {
        int s = __ldg(&g_csr[j]);
        float4 as = ((const float4*)g_as1)[s];
        den.x += __expf(lrelu(as.x + ad4.x));
        den.y += __expf(lrelu(as.y + ad4.y));
        den.z += __expf(lrelu(as.z + ad4.z));
        den.w += __expf(lrelu(as.w + ad4.w));
    }
#pragma unroll
    for (int o = 16; o; o >>= 1) {
        den.x += __shfl_xor_sync(0xffffffffu, den.x, o);
        den.y += __shfl_xor_sync(0xffffffffu, den.y, o);
        den.z += __shfl_xor_sync(0xffffffffu, den.z, o);
        den.w += __shfl_xor_sync(0xffffffffu, den.w, o);
    }
    float4 as_self = ((const float4*)g_as1)[w];
    den.x += __expf(lrelu(as_self.x + ad4.x));
    den.y += __expf(lrelu(as_self.y + ad4.y));
    den.z += __expf(lrelu(as_self.z + ad4.z));
    den.w += __expf(lrelu(as_self.w + ad4.w));
    float denh = (h == 0) ? den.x : (h == 1) ? den.y : (h == 2) ? den.z : den.w;
    float invh = 1.f / denh;
    float ash = (h == 0) ? as_self.x : (h == 1) ? as_self.y : (h == 2) ? as_self.z : as_self.w;
    float wself = __expf(lrelu(ash + adh)) * invh;

    // pass 2: weighted gather from fp16 shadow (256B/edge)
    float4 acc = make_float4(0.f, 0.f, 0.f, 0.f);
    int j = rs;
    for (; j + 1 < re; j += 2) {
        int s0 = __ldg(&g_csr[j]), s1 = __ldg(&g_csr[j + 1]);
        float a0 = g_as1[s0 * 4 + h], a1 = g_as1[s1 * 4 + h];
        uint2 u0 = *(const uint2*)(g_h1h + (long long)s0 * 128 + lane * 4);
        uint2 u1 = *(const uint2*)(g_h1h + (long long)s1 * 128 + lane * 4);
        float w0 = __expf(lrelu(a0 + adh)) * invh;
        float w1 = __expf(lrelu(a1 + adh)) * invh;
        float2 v0a = __half22float2(*(__half2*)&u0.x);
        float2 v0b = __half22float2(*(__half2*)&u0.y);
        float2 v1a = __half22float2(*(__half2*)&u1.x);
        float2 v1b = __half22float2(*(__half2*)&u1.y);
        acc.x += v0a.x * w0 + v1a.x * w1;
        acc.y += v0a.y * w0 + v1a.y * w1;
        acc.z += v0b.x * w0 + v1b.x * w1;
        acc.w += v0b.y * w0 + v1b.y * w1;
    }
    if (j < re) {
        int s = __ldg(&g_csr[j]);
        float a = g_as1[s * 4 + h];
        float ww = __expf(lrelu(a + adh)) * invh;
        uint2 u0 = *(const uint2*)(g_h1h + (long long)s * 128 + lane * 4);
        float2 va = __half22float2(*(__half2*)&u0.x);
        float2 vb = __half22float2(*(__half2*)&u0.y);
        acc.x += va.x * ww; acc.y += va.y * ww; acc.z += vb.x * ww; acc.w += vb.y * ww;
    }
    // self-loop from fp32 h1
    float4 hs = *(const float4*)(g_h1 + (long long)w * 128 + lane * 4);
    float4 bb = ((const float4*)b1)[lane];
    acc.x += hs.x * wself + bb.x;
    acc.y += hs.y * wself + bb.y;
    acc.z += hs.z * wself + bb.z;
    acc.w += hs.w * wself + bb.w;
    acc.x = acc.x > 0.f ? acc.x : (__expf(acc.x) - 1.f);
    acc.y = acc.y > 0.f ? acc.y : (__expf(acc.y) - 1.f);
    acc.z = acc.z > 0.f ? acc.z : (__expf(acc.z) - 1.f);
    acc.w = acc.w > 0.f ? acc.w : (__expf(acc.w) - 1.f);
    *(float4*)(g_out1 + (long long)w * 128 + lane * 4) = acc;
}

// ---------------- GEMM2: h2[N,32] = out1[N,128] @ W2[128,32] ----------------
__global__ void gemm2_kernel(const float* __restrict__ W, int n) {
    __shared__ float xs[64][68];
    __shared__ float ws[64][32];
    int tid = threadIdx.x;   // 128 threads
    int tx = tid & 7, ty = tid >> 3;
    int row0 = blockIdx.x * 64;
    unsigned long long acc2[4][2];
#pragma unroll
    for (int i = 0; i < 4; i++) { acc2[i][0] = 0ull; acc2[i][1] = 0ull; }
    for (int kt = 0; kt < 2; kt++) {
        int kb = kt * 64;
        for (int i = tid; i < 4096; i += 128) {
            int r = i >> 6, k = i & 63;
            int gr = row0 + r;
            xs[k][r] = (gr < n) ? g_out1[(long long)gr * 128 + kb + k] : 0.f;
        }
        for (int i = tid; i < 2048; i += 128) {
            int k = i >> 5, c = i & 31;
            ws[k][c] = W[(kb + k) * 32 + c];
        }
        __syncthreads();
#pragma unroll 8
        for (int k = 0; k < 64; k++) {
            float4 a = *(const float4*)&xs[k][ty * 4];
            unsigned long long b01 = *(const unsigned long long*)&ws[k][tx * 4];
            unsigned long long b23 = *(const unsigned long long*)&ws[k][tx * 4 + 2];
            unsigned long long ad;
            ad = packf2(a.x, a.x); ffma2(acc2[0][0], ad, b01); ffma2(acc2[0][1], ad, b23);
            ad = packf2(a.y, a.y); ffma2(acc2[1][0], ad, b01); ffma2(acc2[1][1], ad, b23);
            ad = packf2(a.z, a.z); ffma2(acc2[2][0], ad, b01); ffma2(acc2[2][1], ad, b23);
            ad = packf2(a.w, a.w); ffma2(acc2[3][0], ad, b01); ffma2(acc2[3][1], ad, b23);
        }
        __syncthreads();
    }
#pragma unroll
    for (int ii = 0; ii < 4; ii++) {
        int gr = row0 + ty * 4 + ii;
        if (gr < n) {
            float2 lo = unpackf2(acc2[ii][0]);
            float2 hi = unpackf2(acc2[ii][1]);
            *(float4*)&g_h2[gr * 32 + tx * 4] = make_float4(lo.x, lo.y, hi.x, hi.y);
            __half2 p0 = __floats2half2_rn(lo.x, lo.y);
            __half2 p1 = __floats2half2_rn(hi.x, hi.y);
            *(uint2*)&g_h2h[gr * 32 + tx * 4] = make_uint2(*(unsigned*)&p0, *(unsigned*)&p1);
        }
    }
}

// ---------------- attention logits layer 2 ----------------
__global__ void att2_kernel(const float4* __restrict__ asr, const float4* __restrict__ adr, int n) {
    int i = blockIdx.x * blockDim.x + threadIdx.x;
    if (i >= n) return;
    const float4* hp = (const float4*)(g_h2 + i * 32);
    float s = 0.f, d = 0.f;
#pragma unroll
    for (int j = 0; j < 8; j++) {
        float4 v = hp[j];
        float4 a = asr[j];
        float4 b = adr[j];
        s += v.x * a.x + v.y * a.y + v.z * a.z + v.w * a.w;
        d += v.x * b.x + v.y * b.y + v.z * b.z + v.w * b.w;
    }
    g_as2[i] = s;
    g_ad2[i] = d;
}

// ---------------- layer2 aggregation + log_softmax: one warp per dst ----------------
__global__ void agg2_kernel(const float* __restrict__ b2, float* __restrict__ out, int n) {
    int w = (blockIdx.x * blockDim.x + threadIdx.x) >> 5;
    int lane = threadIdx.x & 31;
    if (w >= n) return;
    int rs = g_off[w], re = g_off[w + 1];
    float ad = g_ad2[w];

    float den = 0.f;
    for (int j = rs + lane; j < re; j += 32) {
        int s = __ldg(&g_csr[j]);
        den += __expf(lrelu(g_as2[s] + ad));
    }
#pragma unroll
    for (int o = 16; o; o >>= 1) den += __shfl_xor_sync(0xffffffffu, den, o);
    float as_self = g_as2[w];
    den += __expf(lrelu(as_self + ad));
    float inv = 1.f / den;
    float wself = __expf(lrelu(as_self + ad)) * inv;

    // gather from fp16 shadow (64B/edge)
    float acc = 0.f;
    int j = rs;
    for (; j + 1 < re; j += 2) {
        int s0 = __ldg(&g_csr[j]), s1 = __ldg(&g_csr[j + 1]);
        float w0 = __expf(lrelu(g_as2[s0] + ad)) * inv;
        float w1 = __expf(lrelu(g_as2[s1] + ad)) * inv;
        acc += __half2float(g_h2h[s0 * 32 + lane]) * w0
             + __half2float(g_h2h[s1 * 32 + lane]) * w1;
    }
    if (j < re) {
        int s = __ldg(&g_csr[j]);
        float ww = __expf(lrelu(g_as2[s] + ad)) * inv;
        acc += __half2float(g_h2h[s * 32 + lane]) * ww;
    }
    acc += g_h2[w * 32 + lane] * wself + b2[lane];

    float mx = acc;
#pragma unroll
    for (int o = 16; o; o >>= 1) mx = fmaxf(mx, __shfl_xor_sync(0xffffffffu, mx, o));
    float ex = __expf(acc - mx);
    float ssum = ex;
#pragma unroll
    for (int o = 16; o; o >>= 1) ssum += __shfl_xor_sync(0xffffffffu, ssum, o);
    out[(long long)w * 32 + lane] = acc - mx - logf(ssum);
}

extern "C" void kernel_launch(void* const* d_in, const int* in_sizes, int n_in,
                              void* d_out, int out_size) {
    const float* x     = (const float*)d_in[0];
    const int*   ei    = (const int*)d_in[1];
    const float* W1    = (const float*)d_in[2];
    const float* at_s1 = (const float*)d_in[3];
    const float* at_d1 = (const float*)d_in[4];
    const float* b1    = (const float*)d_in[5];
    const float* W2    = (const float*)d_in[6];
    const float* at_s2 = (const float*)d_in[7];
    const float* at_d2 = (const float*)d_in[8];
    const float* b2    = (const float*)d_in[9];
    float* out = (float*)d_out;

    int n = in_sizes[0] / 128;
    int e = in_sizes[1] / 2;
    const int* src = ei;
    const int* dst = ei + e;
    int nb = (n + 255) / 256;

    static cudaStream_t s1 = nullptr;
    static cudaEvent_t evF = nullptr, evJ = nullptr;
    if (s1 == nullptr) {
        cudaStreamCreate(&s1);
        cudaEventCreateWithFlags(&evF, cudaEventDisableTiming);
        cudaEventCreateWithFlags(&evJ, cudaEventDisableTiming);
    }

    // fork: CSR build on s1 (launches 1-3), gemm1 as launch #4 (gets profiled)
    cudaEventRecord(evF, 0);
    cudaStreamWaitEvent(s1, evF, 0);
    zero_deg<<<nb, 256, 0, s1>>>(n);                        // 1
    hist_kernel<<<(e + 255) / 256, 256, 0, s1>>>(dst, e);   // 2
    scan_block<<<nb, 256, 0, s1>>>(n);                      // 3

    dim3 g1((n + 63) / 64, 2);
    gemm1_kernel<<<g1, 256>>>(x, W1, n);                    // 4  <- profiled

    scan_top<<<1, 1024, 0, s1>>>(nb);                       // 5
    scan_add<<<nb, 256, 0, s1>>>(n, e);                     // 6
    fill_kernel<<<(e + 255) / 256, 256, 0, s1>>>(src, dst, e); // 7
    cudaEventRecord(evJ, s1);

    att1_kernel<<<nb, 256>>>((const float4*)at_s1, (const float4*)at_d1, n); // 8

    cudaStreamWaitEvent(0, evJ, 0);
    agg1_kernel<<<(n + 7) / 8, 256>>>(b1, n);               // 9

    gemm2_kernel<<<(n + 63) / 64, 128>>>(W2, n);            // 10
    att2_kernel<<<nb, 256>>>((const float4*)at_s2, (const float4*)at_d2, n); // 11
    agg2_kernel<<<(n + 7) / 8, 256>>>(b2, out, n);          // 12
}

// round 16
// speedup vs baseline: 1.2990x; 1.2990x over previous
#include <cuda_runtime.h>
#include <cuda_fp16.h>
#include <cstdint>

#define NN 100000
#define F1 128
#define HEADS 4
#define OC 32
#define NEG 0.2f
#define MAXE 1700000

// ---------------- scratch (static device globals) ----------------
__device__ __align__(16) float g_h1[NN * F1];
__device__ __align__(16) __half g_h1h[NN * F1];
__device__ __align__(16) float g_out1[NN * F1];
__device__ __align__(16) float g_as1[NN * HEADS];
__device__ __align__(16) float g_ad1[NN * HEADS];
__device__ __align__(16) float g_h2[NN * OC];
__device__ __align__(16) __half g_h2h[NN * OC];
__device__ __align__(16) float g_as2[NN];
__device__ __align__(16) float g_ad2[NN];
__device__ int g_deg[NN];
__device__ int g_off[NN + 1];
__device__ int g_cursor[NN];
__device__ int g_bsum[1024];
__device__ int g_csr[MAXE];

__device__ __forceinline__ float lrelu(float x) { return x > 0.f ? x : NEG * x; }

__device__ __forceinline__ void ffma2(unsigned long long& acc, unsigned long long a, unsigned long long b) {
    asm("fma.rn.f32x2 %0, %1, %2, %3;" : "=l"(acc) : "l"(a), "l"(b), "l"(acc));
}
__device__ __forceinline__ unsigned long long packf2(float lo, float hi) {
    unsigned long long r;
    asm("mov.b64 %0, {%1, %2};" : "=l"(r) : "f"(lo), "f"(hi));
    return r;
}
__device__ __forceinline__ float2 unpackf2(unsigned long long v) {
    float2 r;
    asm("mov.b64 {%0, %1}, %2;" : "=f"(r.x), "=f"(r.y) : "l"(v));
    return r;
}

// ---------------- CSR build ----------------
__global__ void zero_deg(int n) {
    int i = blockIdx.x * blockDim.x + threadIdx.x;
    if (i < n) g_deg[i] = 0;
}
__global__ void hist_kernel(const int* __restrict__ dst, int e) {
    int i = blockIdx.x * blockDim.x + threadIdx.x;
    if (i < e) atomicAdd(&g_deg[dst[i]], 1);
}
__global__ void scan_block(int n) {
    __shared__ int sh[2][256];
    int t = threadIdx.x;
    int i = blockIdx.x * 256 + t;
    int val = (i < n) ? g_deg[i] : 0;
    int cur = 0;
    sh[0][t] = val;
    __syncthreads();
#pragma unroll
    for (int o = 1; o < 256; o <<= 1) {
        int v = sh[cur][t];
        if (t >= o) v += sh[cur][t - o];
        sh[cur ^ 1][t] = v;
        cur ^= 1;
        __syncthreads();
    }
    int incl = sh[cur][t];
    if (i < n) g_off[i] = incl - val;
    if (t == 255) g_bsum[blockIdx.x] = incl;
}
__global__ void scan_top(int nb) {
    __shared__ int sh[2][1024];
    int t = threadIdx.x;
    int val = (t < nb) ? g_bsum[t] : 0;
    int cur = 0;
    sh[0][t] = val;
    __syncthreads();
#pragma unroll
    for (int o = 1; o < 1024; o <<= 1) {
        int v = sh[cur][t];
        if (t >= o) v += sh[cur][t - o];
        sh[cur ^ 1][t] = v;
        cur ^= 1;
        __syncthreads();
    }
    if (t < nb) g_bsum[t] = sh[cur][t] - val;
}
__global__ void scan_add(int n, int e) {
    int i = blockIdx.x * blockDim.x + threadIdx.x;
    if (i < n) {
        int off = g_off[i] + g_bsum[i >> 8];
        g_off[i] = off;
        g_cursor[i] = off;
    }
    if (i == 0) g_off[n] = e;
}
__global__ void fill_kernel(const int* __restrict__ src, const int* __restrict__ dst, int e) {
    int i = blockIdx.x * blockDim.x + threadIdx.x;
    if (i >= e) return;
    int pos = atomicAdd(&g_cursor[dst[i]], 1);
    g_csr[pos] = src[i];
}

// ---------------- GEMM1 (8x8 blocking, f32x2) + fused att1 ----------------
__global__ void __launch_bounds__(256, 2) gemm1_kernel(const float* __restrict__ x,
                                                       const float* __restrict__ W,
                                                       const float* __restrict__ asv,
                                                       const float* __restrict__ adv, int n) {
    __shared__ float xs[32][132];   // [k][row]
    __shared__ float ws[32][136];   // [k][col]
    int tid = threadIdx.x;
    int tx = tid & 15, ty = tid >> 4;
    int row0 = blockIdx.x * 128;
    unsigned long long acc2[8][4];
#pragma unroll
    for (int i = 0; i < 8; i++)
#pragma unroll
        for (int q = 0; q < 4; q++) acc2[i][q] = 0ull;

    for (int kt = 0; kt < 4; kt++) {
        int kb = kt * 32;
#pragma unroll
        for (int pp = 0; pp < 4; pp++) {
            int p = tid + 256 * pp;
            int r = p >> 3, c4 = p & 7;
            int gr = row0 + r;
            float4 v = (gr < n) ? *(const float4*)&x[(long long)gr * 128 + kb + c4 * 4]
                                : make_float4(0.f, 0.f, 0.f, 0.f);
            xs[c4 * 4 + 0][r] = v.x;
            xs[c4 * 4 + 1][r] = v.y;
            xs[c4 * 4 + 2][r] = v.z;
            xs[c4 * 4 + 3][r] = v.w;
        }
#pragma unroll
        for (int pp = 0; pp < 4; pp++) {
            int p = tid + 256 * pp;
            int k = p >> 5, c4 = p & 31;
            *(float4*)&ws[k][c4 * 4] = *(const float4*)&W[(kb + k) * 128 + c4 * 4];
        }
        __syncthreads();
#pragma unroll 8
        for (int k = 0; k < 32; k++) {
            float4 a4a = *(const float4*)&xs[k][ty * 8];
            float4 a4b = *(const float4*)&xs[k][ty * 8 + 4];
            unsigned long long bp0 = *(const unsigned long long*)&ws[k][tx * 8];
            unsigned long long bp1 = *(const unsigned long long*)&ws[k][tx * 8 + 2];
            unsigned long long bp2 = *(const unsigned long long*)&ws[k][tx * 8 + 4];
            unsigned long long bp3 = *(const unsigned long long*)&ws[k][tx * 8 + 6];
            float a[8] = {a4a.x, a4a.y, a4a.z, a4a.w, a4b.x, a4b.y, a4b.z, a4b.w};
#pragma unroll
            for (int i = 0; i < 8; i++) {
                unsigned long long ad = packf2(a[i], a[i]);
                ffma2(acc2[i][0], ad, bp0);
                ffma2(acc2[i][1], ad, bp1);
                ffma2(acc2[i][2], ad, bp2);
                ffma2(acc2[i][3], ad, bp3);
            }
        }
        __syncthreads();
    }

    // epilogue: store h1 fp32 + fp16, fused att1 (cols tx*8..+7 all in head tx>>2)
    int head = tx >> 2;
    float asc[8], adc[8];
#pragma unroll
    for (int c = 0; c < 8; c++) {
        asc[c] = __ldg(&asv[tx * 8 + c]);
        adc[c] = __ldg(&adv[tx * 8 + c]);
    }
#pragma unroll
    for (int i = 0; i < 8; i++) {
        int gr = row0 + ty * 8 + i;
        float2 q0 = unpackf2(acc2[i][0]);
        float2 q1 = unpackf2(acc2[i][1]);
        float2 q2 = unpackf2(acc2[i][2]);
        float2 q3 = unpackf2(acc2[i][3]);
        float v[8] = {q0.x, q0.y, q1.x, q1.y, q2.x, q2.y, q3.x, q3.y};
        float sp = 0.f, dp = 0.f;
#pragma unroll
        for (int c = 0; c < 8; c++) { sp += v[c] * asc[c]; dp += v[c] * adc[c]; }
        sp += __shfl_xor_sync(0xffffffffu, sp, 1);
        sp += __shfl_xor_sync(0xffffffffu, sp, 2);
        dp += __shfl_xor_sync(0xffffffffu, dp, 1);
        dp += __shfl_xor_sync(0xffffffffu, dp, 2);
        if (gr < n) {
            *(float4*)&g_h1[(long long)gr * 128 + tx * 8] = make_float4(v[0], v[1], v[2], v[3]);
            *(float4*)&g_h1[(long long)gr * 128 + tx * 8 + 4] = make_float4(v[4], v[5], v[6], v[7]);
            __half2 p0 = __floats2half2_rn(v[0], v[1]);
            __half2 p1 = __floats2half2_rn(v[2], v[3]);
            __half2 p2 = __floats2half2_rn(v[4], v[5]);
            __half2 p3 = __floats2half2_rn(v[6], v[7]);
            *(uint4*)&g_h1h[(long long)gr * 128 + tx * 8] =
                make_uint4(*(unsigned*)&p0, *(unsigned*)&p1, *(unsigned*)&p2, *(unsigned*)&p3);
            if ((tx & 3) == 0) {
                g_as1[gr * 4 + head] = sp;
                g_ad1[gr * 4 + head] = dp;
            }
        }
    }
}

// ---------------- layer1 aggregation: single-pass, one warp per dst ----------------
__global__ void agg1_kernel(const float* __restrict__ b1, int n) {
    int w = (blockIdx.x * blockDim.x + threadIdx.x) >> 5;
    int lane = threadIdx.x & 31;
    if (w >= n) return;
    int rs = g_off[w], re = g_off[w + 1];
    int h = lane >> 3;
    float adh = g_ad1[w * 4 + h];

    float den = 0.f;
    float4 acc = make_float4(0.f, 0.f, 0.f, 0.f);
    int j = rs;
    for (; j + 3 < re; j += 4) {
        int s0 = __ldg(&g_csr[j]), s1 = __ldg(&g_csr[j + 1]);
        int s2 = __ldg(&g_csr[j + 2]), s3 = __ldg(&g_csr[j + 3]);
        float a0 = __ldg(&g_as1[s0 * 4 + h]), a1 = __ldg(&g_as1[s1 * 4 + h]);
        float a2 = __ldg(&g_as1[s2 * 4 + h]), a3 = __ldg(&g_as1[s3 * 4 + h]);
        uint2 u0 = *(const uint2*)(g_h1h + (long long)s0 * 128 + lane * 4);
        uint2 u1 = *(const uint2*)(g_h1h + (long long)s1 * 128 + lane * 4);
        uint2 u2 = *(const uint2*)(g_h1h + (long long)s2 * 128 + lane * 4);
        uint2 u3 = *(const uint2*)(g_h1h + (long long)s3 * 128 + lane * 4);
        float w0 = __expf(lrelu(a0 + adh));
        float w1 = __expf(lrelu(a1 + adh));
        float w2 = __expf(lrelu(a2 + adh));
        float w3 = __expf(lrelu(a3 + adh));
        den += (w0 + w1) + (w2 + w3);
        float2 va, vb;
        va = __half22float2(*(__half2*)&u0.x); vb = __half22float2(*(__half2*)&u0.y);
        acc.x += va.x * w0; acc.y += va.y * w0; acc.z += vb.x * w0; acc.w += vb.y * w0;
        va = __half22float2(*(__half2*)&u1.x); vb = __half22float2(*(__half2*)&u1.y);
        acc.x += va.x * w1; acc.y += va.y * w1; acc.z += vb.x * w1; acc.w += vb.y * w1;
        va = __half22float2(*(__half2*)&u2.x); vb = __half22float2(*(__half2*)&u2.y);
        acc.x += va.x * w2; acc.y += va.y * w2; acc.z += vb.x * w2; acc.w += vb.y * w2;
        va = __half22float2(*(__half2*)&u3.x); vb = __half22float2(*(__half2*)&u3.y);
        acc.x += va.x * w3; acc.y += va.y * w3; acc.z += vb.x * w3; acc.w += vb.y * w3;
    }
    for (; j < re; j++) {
        int s = __ldg(&g_csr[j]);
        float a = __ldg(&g_as1[s * 4 + h]);
        uint2 u = *(const uint2*)(g_h1h + (long long)s * 128 + lane * 4);
        float ww = __expf(lrelu(a + adh));
        den += ww;
        float2 va = __half22float2(*(__half2*)&u.x);
        float2 vb = __half22float2(*(__half2*)&u.y);
        acc.x += va.x * ww; acc.y += va.y * ww; acc.z += vb.x * ww; acc.w += vb.y * ww;
    }
    float ash = g_as1[w * 4 + h];
    float wself = __expf(lrelu(ash + adh));
    den += wself;
    float inv = 1.f / den;
    float4 hs = *(const float4*)(g_h1 + (long long)w * 128 + lane * 4);
    float4 bb = ((const float4*)b1)[lane];
    acc.x = (acc.x + hs.x * wself) * inv + bb.x;
    acc.y = (acc.y + hs.y * wself) * inv + bb.y;
    acc.z = (acc.z + hs.z * wself) * inv + bb.z;
    acc.w = (acc.w + hs.w * wself) * inv + bb.w;
    acc.x = acc.x > 0.f ? acc.x : (__expf(acc.x) - 1.f);
    acc.y = acc.y > 0.f ? acc.y : (__expf(acc.y) - 1.f);
    acc.z = acc.z > 0.f ? acc.z : (__expf(acc.z) - 1.f);
    acc.w = acc.w > 0.f ? acc.w : (__expf(acc.w) - 1.f);
    *(float4*)(g_out1 + (long long)w * 128 + lane * 4) = acc;
}

// ---------------- GEMM2 (f32x2) + fused att2 ----------------
__global__ void gemm2_kernel(const float* __restrict__ W,
                             const float* __restrict__ asv,
                             const float* __restrict__ adv, int n) {
    __shared__ float xs[64][68];
    __shared__ float ws[64][32];
    int tid = threadIdx.x;   // 128 threads
    int tx = tid & 7, ty = tid >> 3;
    int row0 = blockIdx.x * 64;
    unsigned long long acc2[4][2];
#pragma unroll
    for (int i = 0; i < 4; i++) { acc2[i][0] = 0ull; acc2[i][1] = 0ull; }
    for (int kt = 0; kt < 2; kt++) {
        int kb = kt * 64;
        for (int i = tid; i < 4096; i += 128) {
            int r = i >> 6, k = i & 63;
            int gr = row0 + r;
            xs[k][r] = (gr < n) ? g_out1[(long long)gr * 128 + kb + k] : 0.f;
        }
        for (int i = tid; i < 2048; i += 128) {
            int k = i >> 5, c = i & 31;
            ws[k][c] = W[(kb + k) * 32 + c];
        }
        __syncthreads();
#pragma unroll 8
        for (int k = 0; k < 64; k++) {
            float4 a = *(const float4*)&xs[k][ty * 4];
            unsigned long long b01 = *(const unsigned long long*)&ws[k][tx * 4];
            unsigned long long b23 = *(const unsigned long long*)&ws[k][tx * 4 + 2];
            unsigned long long ad;
            ad = packf2(a.x, a.x); ffma2(acc2[0][0], ad, b01); ffma2(acc2[0][1], ad, b23);
            ad = packf2(a.y, a.y); ffma2(acc2[1][0], ad, b01); ffma2(acc2[1][1], ad, b23);
            ad = packf2(a.z, a.z); ffma2(acc2[2][0], ad, b01); ffma2(acc2[2][1], ad, b23);
            ad = packf2(a.w, a.w); ffma2(acc2[3][0], ad, b01); ffma2(acc2[3][1], ad, b23);
        }
        __syncthreads();
    }
    float asc[4], adc[4];
#pragma unroll
    for (int c = 0; c < 4; c++) {
        asc[c] = __ldg(&asv[tx * 4 + c]);
        adc[c] = __ldg(&adv[tx * 4 + c]);
    }
#pragma unroll
    for (int ii = 0; ii < 4; ii++) {
        int gr = row0 + ty * 4 + ii;
        float2 lo = unpackf2(acc2[ii][0]);
        float2 hi = unpackf2(acc2[ii][1]);
        float v[4] = {lo.x, lo.y, hi.x, hi.y};
        float sp = 0.f, dp = 0.f;
#pragma unroll
        for (int c = 0; c < 4; c++) { sp += v[c] * asc[c]; dp += v[c] * adc[c]; }
        sp += __shfl_xor_sync(0xffffffffu, sp, 1);
        sp += __shfl_xor_sync(0xffffffffu, sp, 2);
        sp += __shfl_xor_sync(0xffffffffu, sp, 4);
        dp += __shfl_xor_sync(0xffffffffu, dp, 1);
        dp += __shfl_xor_sync(0xffffffffu, dp, 2);
        dp += __shfl_xor_sync(0xffffffffu, dp, 4);
        if (gr < n) {
            *(float4*)&g_h2[gr * 32 + tx * 4] = make_float4(v[0], v[1], v[2], v[3]);
            __half2 p0 = __floats2half2_rn(v[0], v[1]);
            __half2 p1 = __floats2half2_rn(v[2], v[3]);
            *(uint2*)&g_h2h[gr * 32 + tx * 4] = make_uint2(*(unsigned*)&p0, *(unsigned*)&p1);
            if (tx == 0) { g_as2[gr] = sp; g_ad2[gr] = dp; }
        }
    }
}

// ---------------- layer2 aggregation + log_softmax: single-pass ----------------
__global__ void agg2_kernel(const float* __restrict__ b2, float* __restrict__ out, int n) {
    int w = (blockIdx.x * blockDim.x + threadIdx.x) >> 5;
    int lane = threadIdx.x & 31;
    if (w >= n) return;
    int rs = g_off[w], re = g_off[w + 1];
    float ad = g_ad2[w];

    float den = 0.f, acc = 0.f;
    int j = rs;
    for (; j + 3 < re; j += 4) {
        int s0 = __ldg(&g_csr[j]), s1 = __ldg(&g_csr[j + 1]);
        int s2 = __ldg(&g_csr[j + 2]), s3 = __ldg(&g_csr[j + 3]);
        float a0 = __ldg(&g_as2[s0]), a1 = __ldg(&g_as2[s1]);
        float a2 = __ldg(&g_as2[s2]), a3 = __ldg(&g_as2[s3]);
        float v0 = __half2float(g_h2h[s0 * 32 + lane]);
        float v1 = __half2float(g_h2h[s1 * 32 + lane]);
        float v2 = __half2float(g_h2h[s2 * 32 + lane]);
        float v3 = __half2float(g_h2h[s3 * 32 + lane]);
        float w0 = __expf(lrelu(a0 + ad));
        float w1 = __expf(lrelu(a1 + ad));
        float w2 = __expf(lrelu(a2 + ad));
        float w3 = __expf(lrelu(a3 + ad));
        den += (w0 + w1) + (w2 + w3);
        acc += v0 * w0 + v1 * w1 + v2 * w2 + v3 * w3;
    }
    for (; j < re; j++) {
        int s = __ldg(&g_csr[j]);
        float ww = __expf(lrelu(__ldg(&g_as2[s]) + ad));
        den += ww;
        acc += __half2float(g_h2h[s * 32 + lane]) * ww;
    }
    float wself = __expf(lrelu(g_as2[w] + ad));
    den += wself;
    float inv = 1.f / den;
    acc = (acc + g_h2[w * 32 + lane] * wself) * inv + b2[lane];

    float mx = acc;
#pragma unroll
    for (int o = 16; o; o >>= 1) mx = fmaxf(mx, __shfl_xor_sync(0xffffffffu, mx, o));
    float ex = __expf(acc - mx);
    float ssum = ex;
#pragma unroll
    for (int o = 16; o; o >>= 1) ssum += __shfl_xor_sync(0xffffffffu, ssum, o);
    out[(long long)w * 32 + lane] = acc - mx - logf(ssum);
}

extern "C" void kernel_launch(void* const* d_in, const int* in_sizes, int n_in,
                              void* d_out, int out_size) {
    const float* x     = (const float*)d_in[0];
    const int*   ei    = (const int*)d_in[1];
    const float* W1    = (const float*)d_in[2];
    const float* at_s1 = (const float*)d_in[3];
    const float* at_d1 = (const float*)d_in[4];
    const float* b1    = (const float*)d_in[5];
    const float* W2    = (const float*)d_in[6];
    const float* at_s2 = (const float*)d_in[7];
    const float* at_d2 = (const float*)d_in[8];
    const float* b2    = (const float*)d_in[9];
    float* out = (float*)d_out;

    int n = in_sizes[0] / 128;
    int e = in_sizes[1] / 2;
    const int* src = ei;
    const int* dst = ei + e;
    int nb = (n + 255) / 256;

    static cudaStream_t s1 = nullptr;
    static cudaEvent_t evF = nullptr, evJ = nullptr;
    if (s1 == nullptr) {
        cudaStreamCreate(&s1);
        cudaEventCreateWithFlags(&evF, cudaEventDisableTiming);
        cudaEventCreateWithFlags(&evJ, cudaEventDisableTiming);
    }

    // fork: CSR build on s1; gemm1 is launch #4 (profiled)
    cudaEventRecord(evF, 0);
    cudaStreamWaitEvent(s1, evF, 0);
    zero_deg<<<nb, 256, 0, s1>>>(n);                          // 1
    hist_kernel<<<(e + 255) / 256, 256, 0, s1>>>(dst, e);     // 2
    scan_block<<<nb, 256, 0, s1>>>(n);                        // 3

    gemm1_kernel<<<(n + 127) / 128, 256>>>(x, W1, at_s1, at_d1, n);  // 4 <- profiled

    scan_top<<<1, 1024, 0, s1>>>(nb);                         // 5
    scan_add<<<nb, 256, 0, s1>>>(n, e);                       // 6
    fill_kernel<<<(e + 255) / 256, 256, 0, s1>>>(src, dst, e); // 7
    cudaEventRecord(evJ, s1);

    cudaStreamWaitEvent(0, evJ, 0);
    agg1_kernel<<<(n + 7) / 8, 256>>>(b1, n);                 // 8

    gemm2_kernel<<<(n + 63) / 64, 128>>>(W2, at_s2, at_d2, n); // 9
    agg2_kernel<<<(n + 7) / 8, 256>>>(b2, out, n);            // 10
}